// round 2
// baseline (speedup 1.0000x reference)
#include <cuda_runtime.h>
#include <math.h>

// Problem constants
#define NB 4096      // batch
#define ND 1024      // feature dim
#define NC 1000      // classes
#define NP 8         // proxies per class
#define NCP 8000     // NC*NP
#define LEN_KEEP 870 // int(1024*0.85)
#define N_MASKED 154 // 1024-870
#define INV_TEMP 10.0f
#define MARGIN 0.3f

// ---------------- scratch (device globals; no allocation allowed) -----------
__device__ float g_featn [NB * ND];       // normalized features
__device__ float g_proxn [NCP * ND];      // normalized proxies (flattened [C*P, D])
__device__ float g_cs    [NB * NC];       // class_sim
__device__ float g_maskf [NB * ND];       // mask (1=kept)
__device__ float g_masked[NB * ND];       // features*mask
__device__ float g_y1    [NB * ND];       // enc pre-LN
__device__ float g_comb  [NB * ND];       // attention-combined proxy
__device__ float g_y2    [NB * ND];       // dec pre-LN
__device__ float g_acc[2];                // [0]=proxy loss sum, [1]=recon loss sum

// ---------------- block reductions (blockDim.x == 256) ----------------------
__device__ __forceinline__ float block_reduce_sum(float v) {
    __shared__ float s_red[8];
    int tid = threadIdx.x;
    #pragma unroll
    for (int o = 16; o; o >>= 1) v += __shfl_xor_sync(0xffffffffu, v, o);
    __syncthreads();
    if ((tid & 31) == 0) s_red[tid >> 5] = v;
    __syncthreads();
    if (tid < 32) {
        float x = (tid < 8) ? s_red[tid] : 0.0f;
        #pragma unroll
        for (int o = 4; o; o >>= 1) x += __shfl_xor_sync(0xffffffffu, x, o);
        if (tid == 0) s_red[0] = x;
    }
    __syncthreads();
    float r = s_red[0];
    __syncthreads();
    return r;
}

__device__ __forceinline__ float block_reduce_max(float v) {
    __shared__ float s_red[8];
    int tid = threadIdx.x;
    #pragma unroll
    for (int o = 16; o; o >>= 1) v = fmaxf(v, __shfl_xor_sync(0xffffffffu, v, o));
    __syncthreads();
    if ((tid & 31) == 0) s_red[tid >> 5] = v;
    __syncthreads();
    if (tid < 32) {
        float x = (tid < 8) ? s_red[tid] : -3.4e38f;
        #pragma unroll
        for (int o = 4; o; o >>= 1) x = fmaxf(x, __shfl_xor_sync(0xffffffffu, x, o));
        if (tid == 0) s_red[0] = x;
    }
    __syncthreads();
    float r = s_red[0];
    __syncthreads();
    return r;
}

// ---------------- init ------------------------------------------------------
__global__ void k_init() { g_acc[0] = 0.0f; g_acc[1] = 0.0f; }

// ---------------- row L2-normalize ------------------------------------------
// which==0 : features [NB,ND] -> g_featn ; which==1 : proxies [NCP,ND] -> g_proxn
__global__ void __launch_bounds__(256) k_normalize(const float* __restrict__ src, int which) {
    int row = blockIdx.x;
    int tid = threadIdx.x;
    const float* s = src + (size_t)row * ND;
    float* dst = (which ? g_proxn : g_featn) + (size_t)row * ND;
    float ss = 0.0f;
    float v[4];
    #pragma unroll
    for (int r = 0; r < 4; r++) { v[r] = s[tid + r * 256]; ss += v[r] * v[r]; }
    ss = block_reduce_sum(ss);
    float norm = sqrtf(ss);
    float scale = 1.0f / fmaxf(norm, 1e-12f);
    #pragma unroll
    for (int r = 0; r < 4; r++) dst[tid + r * 256] = v[r] * scale;
}

// ---------------- SIMT NT-GEMM: C[M,N] = A[M,K] * B[N,K]^T ------------------
// 128x128 block tile, BK=8, 256 threads, 8x8 per-thread microtile.
// SIM=true: fused max-over-8-columns epilogue into class_sim [M, NC].
template <bool SIM>
__device__ __forceinline__ void gemm_body(const float* __restrict__ A,
                                          const float* __restrict__ B,
                                          float* __restrict__ out,
                                          int M, int N, int K) {
    __shared__ float As[8][128];
    __shared__ float Bs[8][128];
    int tid = threadIdx.x;
    int m0 = blockIdx.y * 128;
    int n0 = blockIdx.x * 128;
    int lr = tid >> 1;          // 0..127
    int lc = (tid & 1) * 4;     // 0 or 4
    const float* Aptr = A + (size_t)(m0 + lr) * K + lc;
    bool bvalid = (n0 + lr) < N;
    const float* Bptr = B + (size_t)(bvalid ? (n0 + lr) : 0) * K + lc;
    int ty = tid >> 4, tx = tid & 15;

    float acc[8][8];
    #pragma unroll
    for (int i = 0; i < 8; i++)
        #pragma unroll
        for (int j = 0; j < 8; j++) acc[i][j] = 0.0f;

    for (int k0 = 0; k0 < K; k0 += 8) {
        float4 av = *(const float4*)(Aptr + k0);
        float4 bv = bvalid ? *(const float4*)(Bptr + k0) : make_float4(0, 0, 0, 0);
        __syncthreads();
        As[lc + 0][lr] = av.x; As[lc + 1][lr] = av.y;
        As[lc + 2][lr] = av.z; As[lc + 3][lr] = av.w;
        Bs[lc + 0][lr] = bv.x; Bs[lc + 1][lr] = bv.y;
        Bs[lc + 2][lr] = bv.z; Bs[lc + 3][lr] = bv.w;
        __syncthreads();
        #pragma unroll
        for (int kk = 0; kk < 8; kk++) {
            float a[8], b[8];
            *(float4*)(a)     = *(const float4*)&As[kk][ty * 8];
            *(float4*)(a + 4) = *(const float4*)&As[kk][ty * 8 + 4];
            *(float4*)(b)     = *(const float4*)&Bs[kk][tx * 8];
            *(float4*)(b + 4) = *(const float4*)&Bs[kk][tx * 8 + 4];
            #pragma unroll
            for (int i = 0; i < 8; i++)
                #pragma unroll
                for (int j = 0; j < 8; j++)
                    acc[i][j] = fmaf(a[i], b[j], acc[i][j]);
        }
    }

    if (SIM) {
        // each thread's 8 columns are exactly one class's 8 proxies
        int cls = (n0 + tx * 8) >> 3;
        if (cls < NC) {
            #pragma unroll
            for (int i = 0; i < 8; i++) {
                int row = m0 + ty * 8 + i;
                float m = acc[i][0];
                #pragma unroll
                for (int j = 1; j < 8; j++) m = fmaxf(m, acc[i][j]);
                out[(size_t)row * NC + cls] = m;
            }
        }
    } else {
        #pragma unroll
        for (int i = 0; i < 8; i++) {
            int row = m0 + ty * 8 + i;
            float* dst = out + (size_t)row * N + n0 + tx * 8;
            *(float4*)(dst)     = make_float4(acc[i][0], acc[i][1], acc[i][2], acc[i][3]);
            *(float4*)(dst + 4) = make_float4(acc[i][4], acc[i][5], acc[i][6], acc[i][7]);
        }
    }
}

__global__ void __launch_bounds__(256) k_gemm_sim() {
    gemm_body<true>(g_featn, g_proxn, g_cs, NB, NCP, ND);
}
__global__ void __launch_bounds__(256) k_gemm_enc(const float* __restrict__ enc_w) {
    gemm_body<false>(g_masked, enc_w, g_y1, NB, ND, ND);
}
__global__ void __launch_bounds__(256) k_gemm_dec(const float* __restrict__ dec_w) {
    gemm_body<false>(g_comb, dec_w, g_y2, NB, ND, ND);
}

// ---------------- proxy loss ------------------------------------------------
__global__ void __launch_bounds__(256) k_proxy_loss(const int* __restrict__ labels) {
    int b = blockIdx.x;
    int tid = threadIdx.x;
    int lbl = labels[b];
    const float* row = g_cs + (size_t)b * NC;
    float lm = -3.4e38f;
    for (int i = tid; i < NC; i += 256) {
        float l = row[i];
        if (i == lbl) l -= MARGIN;
        lm = fmaxf(lm, l * INV_TEMP);
    }
    lm = block_reduce_max(lm);
    float se = 0.0f;
    for (int i = tid; i < NC; i += 256) {
        float l = row[i];
        if (i == lbl) l -= MARGIN;
        se += expf(l * INV_TEMP - lm);
    }
    se = block_reduce_sum(se);
    if (tid == 0) {
        float logit_lbl = (row[lbl] - MARGIN) * INV_TEMP;
        float loss = (logf(se) + lm) - logit_lbl;
        atomicAdd(&g_acc[0], loss);
    }
}

// ---------------- mask via exact radix select (matches stable argsort) ------
__global__ void __launch_bounds__(256) k_mask(const float* __restrict__ noise,
                                              const float* __restrict__ features) {
    int b = blockIdx.x;
    int tid = threadIdx.x;
    __shared__ unsigned sh[ND];
    __shared__ int hist[256];
    __shared__ int sel_digit, sel_rem, s_cl;
    const unsigned* nrow = (const unsigned*)(noise) + (size_t)b * ND;
    for (int i = tid; i < ND; i += 256) sh[i] = nrow[i];  // positive floats: bits order = value order
    __syncthreads();

    const int ktarget = LEN_KEEP - 1;  // 0-indexed rank of threshold element
    unsigned prefix = 0;
    int remaining = ktarget;
    for (int shift = 24; shift >= 0; shift -= 8) {
        hist[tid] = 0;
        __syncthreads();
        unsigned pmask = (shift == 24) ? 0u : (0xFFFFFFFFu << (shift + 8));
        for (int i = tid; i < ND; i += 256) {
            unsigned v = sh[i];
            if ((v & pmask) == prefix) atomicAdd(&hist[(v >> shift) & 0xFF], 1);
        }
        __syncthreads();
        if (tid == 0) {
            int cum = 0, d = 0;
            for (; d < 256; d++) {
                int h = hist[d];
                if (cum + h > remaining) break;
                cum += h;
            }
            sel_digit = d;
            sel_rem = remaining - cum;
        }
        __syncthreads();
        prefix |= ((unsigned)sel_digit) << shift;
        remaining = sel_rem;
        __syncthreads();
    }
    unsigned T = prefix;

    // count strictly less, get quota for ties at T (stable argsort: lower index wins)
    if (tid == 0) s_cl = 0;
    __syncthreads();
    int local = 0;
    for (int i = tid; i < ND; i += 256) if (sh[i] < T) local++;
    atomicAdd(&s_cl, local);
    __syncthreads();
    int quota = LEN_KEEP - s_cl;

    for (int i = tid; i < ND; i += 256) {
        unsigned v = sh[i];
        float m;
        if (v < T) {
            m = 1.0f;
        } else if (v > T) {
            m = 0.0f;
        } else {
            // tie on threshold bits (rare with random floats): stable rank by index
            int r = 0;
            for (int j = 0; j < i; j++) r += (sh[j] == T) ? 1 : 0;
            m = (r < quota) ? 1.0f : 0.0f;
        }
        size_t idx = (size_t)b * ND + i;
        g_maskf[idx] = m;
        g_masked[idx] = features[idx] * m;
    }
}

// ---------------- enc LN + ReLU + proxy attention (fused per row) -----------
__global__ void __launch_bounds__(256) k_ln_att(const float* __restrict__ enc_b,
                                                const float* __restrict__ enc_g,
                                                const float* __restrict__ enc_beta,
                                                const int* __restrict__ labels) {
    int b = blockIdx.x;
    int tid = threadIdx.x;
    __shared__ float e[ND];
    __shared__ float sdot[NP];
    float v[4], s = 0.0f, s2 = 0.0f;
    #pragma unroll
    for (int r = 0; r < 4; r++) {
        int i = tid + r * 256;
        float x = g_y1[(size_t)b * ND + i] + enc_b[i];
        v[r] = x; s += x; s2 += x * x;
    }
    s = block_reduce_sum(s);
    s2 = block_reduce_sum(s2);
    float mean = s * (1.0f / ND);
    float var = s2 * (1.0f / ND) - mean * mean;
    float rs = rsqrtf(var + 1e-5f);
    #pragma unroll
    for (int r = 0; r < 4; r++) {
        int i = tid + r * 256;
        float x = (v[r] - mean) * rs * enc_g[i] + enc_beta[i];
        e[i] = fmaxf(x, 0.0f);
    }
    __syncthreads();

    const float* P = g_proxn + (size_t)labels[b] * (NP * ND);
    float part[NP];
    #pragma unroll
    for (int p = 0; p < NP; p++) part[p] = 0.0f;
    #pragma unroll
    for (int r = 0; r < 4; r++) {
        int i = tid + r * 256;
        float ev = e[i];
        #pragma unroll
        for (int p = 0; p < NP; p++) part[p] += P[p * ND + i] * ev;
    }
    #pragma unroll
    for (int p = 0; p < NP; p++) {
        float d = block_reduce_sum(part[p]);
        if (tid == 0) sdot[p] = d;
    }
    __syncthreads();

    float m = -3.4e38f;
    #pragma unroll
    for (int p = 0; p < NP; p++) m = fmaxf(m, sdot[p] * INV_TEMP);
    float w[NP], ws = 0.0f;
    #pragma unroll
    for (int p = 0; p < NP; p++) { w[p] = expf(sdot[p] * INV_TEMP - m); ws += w[p]; }
    float inv_ws = 1.0f / ws;
    #pragma unroll
    for (int r = 0; r < 4; r++) {
        int i = tid + r * 256;
        float c = 0.0f;
        #pragma unroll
        for (int p = 0; p < NP; p++) c += w[p] * P[p * ND + i];
        g_comb[(size_t)b * ND + i] = c * inv_ws;
    }
}

// ---------------- dec LN + masked recon loss (fused per row) ----------------
__global__ void __launch_bounds__(256) k_recon(const float* __restrict__ dec_b,
                                               const float* __restrict__ dec_g,
                                               const float* __restrict__ dec_beta,
                                               const float* __restrict__ features) {
    int b = blockIdx.x;
    int tid = threadIdx.x;
    float v[4], s = 0.0f, s2 = 0.0f;
    #pragma unroll
    for (int r = 0; r < 4; r++) {
        int i = tid + r * 256;
        float x = g_y2[(size_t)b * ND + i] + dec_b[i];
        v[r] = x; s += x; s2 += x * x;
    }
    s = block_reduce_sum(s);
    s2 = block_reduce_sum(s2);
    float mean = s * (1.0f / ND);
    float var = s2 * (1.0f / ND) - mean * mean;
    float rs = rsqrtf(var + 1e-5f);
    float se = 0.0f;
    #pragma unroll
    for (int r = 0; r < 4; r++) {
        int i = tid + r * 256;
        size_t idx = (size_t)b * ND + i;
        float recon = (v[r] - mean) * rs * dec_g[i] + dec_beta[i];
        float d = recon - features[idx];
        se += d * d * (1.0f - g_maskf[idx]);
    }
    se = block_reduce_sum(se);
    if (tid == 0) atomicAdd(&g_acc[1], se * (1.0f / (float)N_MASKED));
}

// ---------------- final -----------------------------------------------------
__global__ void k_final(float* __restrict__ out) {
    out[0] = (g_acc[0] + g_acc[1]) * (1.0f / (float)NB);
}

// ---------------- launch ----------------------------------------------------
extern "C" void kernel_launch(void* const* d_in, const int* in_sizes, int n_in,
                              void* d_out, int out_size) {
    const float* features = (const float*)d_in[0];
    const float* proxies  = (const float*)d_in[1];
    const float* noise    = (const float*)d_in[2];
    const float* enc_w    = (const float*)d_in[3];
    const float* enc_b    = (const float*)d_in[4];
    const float* enc_g    = (const float*)d_in[5];
    const float* enc_beta = (const float*)d_in[6];
    const float* dec_w    = (const float*)d_in[7];
    const float* dec_b    = (const float*)d_in[8];
    const float* dec_g    = (const float*)d_in[9];
    const float* dec_beta = (const float*)d_in[10];
    const int*   labels   = (const int*)d_in[11];
    float* out = (float*)d_out;

    k_init<<<1, 1>>>();
    k_normalize<<<NB, 256>>>(features, 0);
    k_normalize<<<NCP, 256>>>(proxies, 1);

    dim3 gsim((NCP + 127) / 128, NB / 128);  // 63 x 32
    k_gemm_sim<<<gsim, 256>>>();
    k_proxy_loss<<<NB, 256>>>(labels);

    k_mask<<<NB, 256>>>(noise, features);
    dim3 gsq(ND / 128, NB / 128);            // 8 x 32
    k_gemm_enc<<<gsq, 256>>>(enc_w);
    k_ln_att<<<NB, 256>>>(enc_b, enc_g, enc_beta, labels);
    k_gemm_dec<<<gsq, 256>>>(dec_w);
    k_recon<<<NB, 256>>>(dec_b, dec_g, dec_beta, features);

    k_final<<<1, 1>>>(out);
}

// round 4
// speedup vs baseline: 4.8731x; 4.8731x over previous
#include <cuda_runtime.h>
#include <cuda_bf16.h>
#include <math.h>
#include <stdint.h>

// Problem constants
#define NB 4096
#define ND 1024
#define NC 1000
#define NP 8
#define NCP 8000
#define LEN_KEEP 870
#define N_MASKED 154
#define INV_TEMP 10.0f
#define MARGIN 0.3f

// ================= scratch (device globals) =================================
__device__ __nv_bfloat16 g_fA[NB * ND];     // normalized features (bf16)
__device__ __nv_bfloat16 g_pB[NCP * ND];    // normalized proxies (bf16)
__device__ float         g_proxn[NCP * ND]; // normalized proxies fp32 (for attention)
__device__ __nv_bfloat16 g_mA[NB * ND];     // masked features (bf16)
__device__ __nv_bfloat16 g_cA[NB * ND];     // attention-combined (bf16)
__device__ __nv_bfloat16 g_ewb[ND * ND];    // enc_w bf16
__device__ __nv_bfloat16 g_dwb[ND * ND];    // dec_w bf16
__device__ float g_cs[NB * NC];
__device__ float g_maskf[NB * ND];
__device__ float g_y1[NB * ND];
__device__ float g_y2[NB * ND];
__device__ float g_acc[2];

__device__ __forceinline__ uint32_t smem_u32(const void* p) {
    uint32_t a;
    asm("{ .reg .u64 t; cvta.to.shared.u64 t, %1; cvt.u32.u64 %0, t; }" : "=r"(a) : "l"(p));
    return a;
}

// ================= block reductions (blockDim == 256) =======================
__device__ __forceinline__ float block_reduce_sum(float v) {
    __shared__ float s_red[8];
    int tid = threadIdx.x;
    #pragma unroll
    for (int o = 16; o; o >>= 1) v += __shfl_xor_sync(0xffffffffu, v, o);
    __syncthreads();
    if ((tid & 31) == 0) s_red[tid >> 5] = v;
    __syncthreads();
    if (tid < 32) {
        float x = (tid < 8) ? s_red[tid] : 0.0f;
        #pragma unroll
        for (int o = 4; o; o >>= 1) x += __shfl_xor_sync(0xffffffffu, x, o);
        if (tid == 0) s_red[0] = x;
    }
    __syncthreads();
    float r = s_red[0];
    __syncthreads();
    return r;
}
__device__ __forceinline__ float block_reduce_max(float v) {
    __shared__ float s_red[8];
    int tid = threadIdx.x;
    #pragma unroll
    for (int o = 16; o; o >>= 1) v = fmaxf(v, __shfl_xor_sync(0xffffffffu, v, o));
    __syncthreads();
    if ((tid & 31) == 0) s_red[tid >> 5] = v;
    __syncthreads();
    if (tid < 32) {
        float x = (tid < 8) ? s_red[tid] : -3.4e38f;
        #pragma unroll
        for (int o = 4; o; o >>= 1) x = fmaxf(x, __shfl_xor_sync(0xffffffffu, x, o));
        if (tid == 0) s_red[0] = x;
    }
    __syncthreads();
    float r = s_red[0];
    __syncthreads();
    return r;
}

// ================= small kernels ============================================
__global__ void k_init() { g_acc[0] = 0.0f; g_acc[1] = 0.0f; }

__global__ void __launch_bounds__(256) k_norm_feat(const float* __restrict__ src) {
    int row = blockIdx.x, tid = threadIdx.x;
    const float* s = src + (size_t)row * ND;
    float v[4], ss = 0.0f;
    #pragma unroll
    for (int r = 0; r < 4; r++) { v[r] = s[tid + r * 256]; ss += v[r] * v[r]; }
    ss = block_reduce_sum(ss);
    float scale = 1.0f / fmaxf(sqrtf(ss), 1e-12f);
    #pragma unroll
    for (int r = 0; r < 4; r++)
        g_fA[(size_t)row * ND + tid + r * 256] = __float2bfloat16_rn(v[r] * scale);
}

__global__ void __launch_bounds__(256) k_norm_prox(const float* __restrict__ src) {
    int row = blockIdx.x, tid = threadIdx.x;
    const float* s = src + (size_t)row * ND;
    float v[4], ss = 0.0f;
    #pragma unroll
    for (int r = 0; r < 4; r++) { v[r] = s[tid + r * 256]; ss += v[r] * v[r]; }
    ss = block_reduce_sum(ss);
    float scale = 1.0f / fmaxf(sqrtf(ss), 1e-12f);
    #pragma unroll
    for (int r = 0; r < 4; r++) {
        size_t i = (size_t)row * ND + tid + r * 256;
        float x = v[r] * scale;
        g_proxn[i] = x;
        g_pB[i] = __float2bfloat16_rn(x);
    }
}

__global__ void __launch_bounds__(256) k_conv_w(const float* __restrict__ ew,
                                                const float* __restrict__ dw) {
    int i = blockIdx.x * 256 + threadIdx.x;
    int stride = gridDim.x * 256;
    for (; i < ND * ND; i += stride) {
        g_ewb[i] = __float2bfloat16_rn(ew[i]);
        g_dwb[i] = __float2bfloat16_rn(dw[i]);
    }
}

// ================= HMMA bf16 GEMM: C[M,N] = A[M,K] * B[N,K]^T ===============
// 128x128 block tile, BK=32, 256 thr (8 warps 2x4), warp 64x32 = 4x4 m16n8k16
// MODE 0: sim (max-over-8-proxy epilogue -> g_cs)
// MODE 1: enc -> g_y1 ; MODE 2: dec -> g_y2
#define RSTRIDE_B 80            // bytes per SMEM row (32 bf16 + 8 pad)
#define ABYTES (128 * RSTRIDE_B)

template <int MODE>
__global__ void __launch_bounds__(256) k_gemm() {
    __shared__ __align__(16) char smem[4 * ABYTES];  // A0 B0 A1 B1
    const __nv_bfloat16* A = (MODE == 0) ? g_fA : (MODE == 1) ? g_mA : g_cA;
    const __nv_bfloat16* B = (MODE == 0) ? g_pB : (MODE == 1) ? g_ewb : g_dwb;
    const int nrowsB = (MODE == 0) ? NCP : ND;

    int tid = threadIdx.x, lane = tid & 31, wid = tid >> 5;
    int wr = wid & 1, wc = wid >> 1;
    int m0 = blockIdx.y * 128, n0 = blockIdx.x * 128;
    uint32_t sb = smem_u32(smem);

    // per-lane ldmatrix offsets
    int aRow = (lane & 7) | (((lane >> 3) & 1) << 3);
    uint32_t aOffBase = (uint32_t)((wr * 64 + aRow) * RSTRIDE_B + (lane >> 4) * 16);
    uint32_t bOffBase = (uint32_t)((wc * 32 + (lane & 7)) * RSTRIDE_B + ((lane >> 3) & 1) * 16);

    float acc[4][4][4];
    #pragma unroll
    for (int i = 0; i < 4; i++)
        #pragma unroll
        for (int j = 0; j < 4; j++)
            #pragma unroll
            for (int q = 0; q < 4; q++) acc[i][j][q] = 0.0f;

    const int NCHUNK = ND / 32;

    // chunk loader (cp.async)
    auto load_chunk = [&](int c, int buf) {
        int kb = c * 32;
        uint32_t a_s = sb + (uint32_t)(buf * 2 * ABYTES);
        uint32_t b_s = a_s + ABYTES;
        #pragma unroll
        for (int j = 0; j < 2; j++) {
            int u = tid + j * 256;
            int row = u >> 2, seg = u & 3;
            uint32_t sa = a_s + row * RSTRIDE_B + seg * 16;
            const void* ga = A + (size_t)(m0 + row) * ND + kb + seg * 8;
            asm volatile("cp.async.cg.shared.global [%0], [%1], 16;" :: "r"(sa), "l"(ga));
            int grow = n0 + row;
            uint32_t sbb = b_s + row * RSTRIDE_B + seg * 16;
            const void* gb = B + (size_t)(grow < nrowsB ? grow : 0) * ND + kb + seg * 8;
            int srcsz = (grow < nrowsB) ? 16 : 0;
            asm volatile("cp.async.cg.shared.global [%0], [%1], 16, %2;" :: "r"(sbb), "l"(gb), "r"(srcsz));
        }
        asm volatile("cp.async.commit_group;" ::: "memory");
    };

    load_chunk(0, 0);
    for (int c = 0; c < NCHUNK; c++) {
        asm volatile("cp.async.wait_group 0;" ::: "memory");
        __syncthreads();
        if (c + 1 < NCHUNK) load_chunk(c + 1, (c + 1) & 1);
        uint32_t a_s = sb + (uint32_t)((c & 1) * 2 * ABYTES);
        uint32_t b_s = a_s + ABYTES;
        #pragma unroll
        for (int kk = 0; kk < 2; kk++) {
            uint32_t afr[4][4], bfr[4][2];
            #pragma unroll
            for (int mt = 0; mt < 4; mt++) {
                uint32_t ad = a_s + aOffBase + mt * 16 * RSTRIDE_B + kk * 32;
                asm volatile("ldmatrix.sync.aligned.m8n8.x4.shared.b16 {%0,%1,%2,%3}, [%4];"
                             : "=r"(afr[mt][0]), "=r"(afr[mt][1]), "=r"(afr[mt][2]), "=r"(afr[mt][3])
                             : "r"(ad));
            }
            #pragma unroll
            for (int nt = 0; nt < 4; nt++) {
                uint32_t bd = b_s + bOffBase + nt * 8 * RSTRIDE_B + kk * 32;
                asm volatile("ldmatrix.sync.aligned.m8n8.x2.shared.b16 {%0,%1}, [%2];"
                             : "=r"(bfr[nt][0]), "=r"(bfr[nt][1]) : "r"(bd));
            }
            #pragma unroll
            for (int mt = 0; mt < 4; mt++)
                #pragma unroll
                for (int nt = 0; nt < 4; nt++)
                    asm volatile("mma.sync.aligned.m16n8k16.row.col.f32.bf16.bf16.f32 "
                                 "{%0,%1,%2,%3}, {%4,%5,%6,%7}, {%8,%9}, {%0,%1,%2,%3};"
                                 : "+f"(acc[mt][nt][0]), "+f"(acc[mt][nt][1]),
                                   "+f"(acc[mt][nt][2]), "+f"(acc[mt][nt][3])
                                 : "r"(afr[mt][0]), "r"(afr[mt][1]), "r"(afr[mt][2]), "r"(afr[mt][3]),
                                   "r"(bfr[nt][0]), "r"(bfr[nt][1]));
        }
        __syncthreads();
    }

    int qr = lane >> 2, qc = lane & 3;
    if (MODE == 0) {
        #pragma unroll
        for (int mt = 0; mt < 4; mt++) {
            #pragma unroll
            for (int nt = 0; nt < 4; nt++) {
                float v0 = fmaxf(acc[mt][nt][0], acc[mt][nt][1]);
                float v1 = fmaxf(acc[mt][nt][2], acc[mt][nt][3]);
                v0 = fmaxf(v0, __shfl_xor_sync(0xffffffffu, v0, 1));
                v0 = fmaxf(v0, __shfl_xor_sync(0xffffffffu, v0, 2));
                v1 = fmaxf(v1, __shfl_xor_sync(0xffffffffu, v1, 1));
                v1 = fmaxf(v1, __shfl_xor_sync(0xffffffffu, v1, 2));
                int cls = (n0 + wc * 32 + nt * 8) >> 3;
                if (qc == 0 && cls < NC) {
                    int r0 = m0 + wr * 64 + mt * 16 + qr;
                    g_cs[(size_t)r0 * NC + cls] = v0;
                    g_cs[(size_t)(r0 + 8) * NC + cls] = v1;
                }
            }
        }
    } else {
        float* Y = (MODE == 1) ? g_y1 : g_y2;
        #pragma unroll
        for (int mt = 0; mt < 4; mt++) {
            int r0 = m0 + wr * 64 + mt * 16 + qr;
            #pragma unroll
            for (int nt = 0; nt < 4; nt++) {
                int ncol = n0 + wc * 32 + nt * 8 + qc * 2;
                *(float2*)(Y + (size_t)r0 * ND + ncol) =
                    make_float2(acc[mt][nt][0], acc[mt][nt][1]);
                *(float2*)(Y + (size_t)(r0 + 8) * ND + ncol) =
                    make_float2(acc[mt][nt][2], acc[mt][nt][3]);
            }
        }
    }
}

// ================= proxy loss ===============================================
__global__ void __launch_bounds__(256) k_proxy_loss(const int* __restrict__ labels) {
    int b = blockIdx.x, tid = threadIdx.x;
    int lbl = labels[b];
    const float* row = g_cs + (size_t)b * NC;
    float lm = -3.4e38f;
    for (int i = tid; i < NC; i += 256) {
        float l = row[i];
        if (i == lbl) l -= MARGIN;
        lm = fmaxf(lm, l * INV_TEMP);
    }
    lm = block_reduce_max(lm);
    float se = 0.0f;
    for (int i = tid; i < NC; i += 256) {
        float l = row[i];
        if (i == lbl) l -= MARGIN;
        se += expf(l * INV_TEMP - lm);
    }
    se = block_reduce_sum(se);
    if (tid == 0) {
        float logit_lbl = (row[lbl] - MARGIN) * INV_TEMP;
        atomicAdd(&g_acc[0], (logf(se) + lm) - logit_lbl);
    }
}

// ================= mask (exact radix select over noise bits) ================
__global__ void __launch_bounds__(256) k_mask(const float* __restrict__ noise,
                                              const float* __restrict__ features) {
    int b = blockIdx.x, tid = threadIdx.x;
    __shared__ unsigned sh[ND];
    __shared__ int hist[256];
    __shared__ int sel_digit, sel_rem, s_cl;
    const unsigned* nrow = (const unsigned*)noise + (size_t)b * ND;
    for (int i = tid; i < ND; i += 256) sh[i] = nrow[i];
    __syncthreads();

    unsigned prefix = 0;
    int remaining = LEN_KEEP - 1;
    for (int shift = 24; shift >= 0; shift -= 8) {
        hist[tid] = 0;
        __syncthreads();
        unsigned pmask = (shift == 24) ? 0u : (0xFFFFFFFFu << (shift + 8));
        for (int i = tid; i < ND; i += 256) {
            unsigned v = sh[i];
            if ((v & pmask) == prefix) atomicAdd(&hist[(v >> shift) & 0xFF], 1);
        }
        __syncthreads();
        if (tid == 0) {
            int cum = 0, d = 0;
            for (; d < 256; d++) {
                int h = hist[d];
                if (cum + h > remaining) break;
                cum += h;
            }
            sel_digit = d; sel_rem = remaining - cum;
        }
        __syncthreads();
        prefix |= ((unsigned)sel_digit) << shift;
        remaining = sel_rem;
        __syncthreads();
    }
    unsigned T = prefix;

    if (tid == 0) s_cl = 0;
    __syncthreads();
    int local = 0;
    for (int i = tid; i < ND; i += 256) if (sh[i] < T) local++;
    atomicAdd(&s_cl, local);
    __syncthreads();
    int quota = LEN_KEEP - s_cl;

    for (int i = tid; i < ND; i += 256) {
        unsigned v = sh[i];
        float m;
        if (v < T) m = 1.0f;
        else if (v > T) m = 0.0f;
        else {
            int r = 0;
            for (int j = 0; j < i; j++) r += (sh[j] == T) ? 1 : 0;
            m = (r < quota) ? 1.0f : 0.0f;
        }
        size_t idx = (size_t)b * ND + i;
        g_maskf[idx] = m;
        g_mA[idx] = __float2bfloat16_rn(features[idx] * m);
    }
}

// ================= enc LN + ReLU + proxy attention ==========================
__global__ void __launch_bounds__(256) k_ln_att(const float* __restrict__ enc_b,
                                                const float* __restrict__ enc_g,
                                                const float* __restrict__ enc_beta,
                                                const int* __restrict__ labels) {
    int b = blockIdx.x, tid = threadIdx.x;
    __shared__ float e[ND];
    __shared__ float sdot[NP];
    float v[4], s = 0.0f, s2 = 0.0f;
    #pragma unroll
    for (int r = 0; r < 4; r++) {
        int i = tid + r * 256;
        float x = g_y1[(size_t)b * ND + i] + enc_b[i];
        v[r] = x; s += x; s2 += x * x;
    }
    s = block_reduce_sum(s);
    s2 = block_reduce_sum(s2);
    float mean = s * (1.0f / ND);
    float var = s2 * (1.0f / ND) - mean * mean;
    float rs = rsqrtf(var + 1e-5f);
    #pragma unroll
    for (int r = 0; r < 4; r++) {
        int i = tid + r * 256;
        e[i] = fmaxf((v[r] - mean) * rs * enc_g[i] + enc_beta[i], 0.0f);
    }
    __syncthreads();

    const float* P = g_proxn + (size_t)labels[b] * (NP * ND);
    float part[NP];
    #pragma unroll
    for (int p = 0; p < NP; p++) part[p] = 0.0f;
    #pragma unroll
    for (int r = 0; r < 4; r++) {
        int i = tid + r * 256;
        float ev = e[i];
        #pragma unroll
        for (int p = 0; p < NP; p++) part[p] += P[p * ND + i] * ev;
    }
    #pragma unroll
    for (int p = 0; p < NP; p++) {
        float d = block_reduce_sum(part[p]);
        if (tid == 0) sdot[p] = d;
    }
    __syncthreads();

    float m = -3.4e38f;
    #pragma unroll
    for (int p = 0; p < NP; p++) m = fmaxf(m, sdot[p] * INV_TEMP);
    float w[NP], ws = 0.0f;
    #pragma unroll
    for (int p = 0; p < NP; p++) { w[p] = expf(sdot[p] * INV_TEMP - m); ws += w[p]; }
    float inv_ws = 1.0f / ws;
    #pragma unroll
    for (int r = 0; r < 4; r++) {
        int i = tid + r * 256;
        float c = 0.0f;
        #pragma unroll
        for (int p = 0; p < NP; p++) c += w[p] * P[p * ND + i];
        g_cA[(size_t)b * ND + i] = __float2bfloat16_rn(c * inv_ws);
    }
}

// ================= dec LN + masked recon loss ===============================
__global__ void __launch_bounds__(256) k_recon(const float* __restrict__ dec_b,
                                               const float* __restrict__ dec_g,
                                               const float* __restrict__ dec_beta,
                                               const float* __restrict__ features) {
    int b = blockIdx.x, tid = threadIdx.x;
    float v[4], s = 0.0f, s2 = 0.0f;
    #pragma unroll
    for (int r = 0; r < 4; r++) {
        int i = tid + r * 256;
        float x = g_y2[(size_t)b * ND + i] + dec_b[i];
        v[r] = x; s += x; s2 += x * x;
    }
    s = block_reduce_sum(s);
    s2 = block_reduce_sum(s2);
    float mean = s * (1.0f / ND);
    float var = s2 * (1.0f / ND) - mean * mean;
    float rs = rsqrtf(var + 1e-5f);
    float se = 0.0f;
    #pragma unroll
    for (int r = 0; r < 4; r++) {
        int i = tid + r * 256;
        size_t idx = (size_t)b * ND + i;
        float recon = (v[r] - mean) * rs * dec_g[i] + dec_beta[i];
        float d = recon - features[idx];
        se += d * d * (1.0f - g_maskf[idx]);
    }
    se = block_reduce_sum(se);
    if (tid == 0) atomicAdd(&g_acc[1], se * (1.0f / (float)N_MASKED));
}

__global__ void k_final(float* __restrict__ out) {
    out[0] = (g_acc[0] + g_acc[1]) * (1.0f / (float)NB);
}

// ================= launch ===================================================
extern "C" void kernel_launch(void* const* d_in, const int* in_sizes, int n_in,
                              void* d_out, int out_size) {
    const float* features = (const float*)d_in[0];
    const float* proxies  = (const float*)d_in[1];
    const float* noise    = (const float*)d_in[2];
    const float* enc_w    = (const float*)d_in[3];
    const float* enc_b    = (const float*)d_in[4];
    const float* enc_g    = (const float*)d_in[5];
    const float* enc_beta = (const float*)d_in[6];
    const float* dec_w    = (const float*)d_in[7];
    const float* dec_b    = (const float*)d_in[8];
    const float* dec_g    = (const float*)d_in[9];
    const float* dec_beta = (const float*)d_in[10];
    const int*   labels   = (const int*)d_in[11];
    float* out = (float*)d_out;

    k_init<<<1, 1>>>();
    k_norm_feat<<<NB, 256>>>(features);
    k_norm_prox<<<NCP, 256>>>(proxies);
    k_conv_w<<<1024, 256>>>(enc_w, dec_w);
    k_mask<<<NB, 256>>>(noise, features);

    k_gemm<0><<<dim3(63, 32), 256>>>();   // sim -> g_cs
    k_proxy_loss<<<NB, 256>>>(labels);

    k_gemm<1><<<dim3(8, 32), 256>>>();    // enc -> g_y1
    k_ln_att<<<NB, 256>>>(enc_b, enc_g, enc_beta, labels);
    k_gemm<2><<<dim3(8, 32), 256>>>();    // dec -> g_y2
    k_recon<<<NB, 256>>>(dec_b, dec_g, dec_beta, features);

    k_final<<<1, 1>>>(out);
}